// round 1
// baseline (speedup 1.0000x reference)
#include <cuda_runtime.h>
#include <math.h>
#include <stdint.h>

// ============================================================================
// ClassificationLoss (OHEM-style): B=16 images, N=1M anchors each.
//   pos_loss  = -sum_{pos} log_c(conf)
//   hard_loss = -sum over top-512 negative confs of log_c(1-v)
//   rand_loss = -sum over 512 random remaining negatives (chosen by the 512
//               smallest rand_u[j], j < num_neg-512; value = (512+j)-th
//               largest negative conf) of log_c(1-v)
//   out[b] = pos+hard+rand   (num_neg-512 > 0 always holds here; the
//            degenerate branch is still implemented)
//
// Strategy: histogram-based exact value-at-rank selection instead of sorting.
// ============================================================================

#define BB 16
#define NN (1 << 20)            // anchors per image
#define NB (1 << 17)            // fine histogram bins (linear over [0,1))
#define NBC 1024                // coarse bins
#define FPC (NB / NBC)          // fine bins per coarse = 128
#define NU (NN - 512)           // rand_u length per image
#define CAP_CAND 32768
#define T0 0.002f               // candidate threshold for smallest-u selection
#define MAXQ 1024               // 512 hard + 512 rand rank queries
#define SLOTS 2048
#define SLOTC 64

// -------- scratch (static device globals; no dynamic allocation) -----------
__device__ int   g_hist[BB][NB];            // 8 MB
__device__ int   g_coarse[BB][NBC];
__device__ int   g_slotid[BB][NB];          // 8 MB, -1 = bin not interesting
__device__ float g_slotbuf[BB][SLOTS][SLOTC]; // 8 MB
__device__ int   g_slotcnt[BB][SLOTS];
__device__ int   g_nslots[BB];
__device__ int   g_numpos[BB];
__device__ float g_acc_ph[BB];              // pos_loss + hard_loss
__device__ float g_acc_r[BB];               // rand_loss
__device__ float g_cand_u[BB][CAP_CAND];
__device__ int   g_cand_j[BB][CAP_CAND];
__device__ int   g_candcnt[BB];
__device__ int   g_qrank[BB][MAXQ];
__device__ int   g_qbin[BB][MAXQ];
__device__ int   g_qt[BB][MAXQ];
__device__ int   g_qcnt[BB];

__device__ __forceinline__ float log_c(float x) {
    // jnp.clip(log(x), -100, None); log(0) = -inf -> -100
    return fmaxf(logf(x), -100.0f);
}

__device__ __forceinline__ int conf_bin(float v) {
    int b = (int)(v * (float)NB);
    if (b < 0) b = 0;
    if (b >= NB) b = NB - 1;
    return b;
}

// ---------------------------------------------------------------------------
__global__ void k_init() {
    int tid = blockIdx.x * blockDim.x + threadIdx.x;
    int nthreads = gridDim.x * blockDim.x;
    const int total = BB * NB;
    for (int i = tid; i < total; i += nthreads) {
        int b = i >> 17, bin = i & (NB - 1);
        g_hist[b][bin] = 0;
        g_slotid[b][bin] = -1;
    }
    if (tid < BB * SLOTS) g_slotcnt[tid / SLOTS][tid % SLOTS] = 0;
    if (tid < BB * MAXQ) {
        int b = tid / MAXQ, q = tid % MAXQ;
        if (q < 512) g_qrank[b][q] = q;   // hard ranks 0..511
        g_qbin[b][q] = -1;
    }
    if (tid < BB) {
        g_nslots[tid] = 0;
        g_numpos[tid] = 0;
        g_acc_ph[tid] = 0.0f;
        g_acc_r[tid]  = 0.0f;
        g_candcnt[tid] = 0;
        g_qcnt[tid] = 512;                // rand queries appended after
    }
}

// ---------------------------------------------------------------------------
// Pass 1: per image — count positives, accumulate pos_loss, histogram negs.
// pos_indicator arrives as float32(0/1) or int32(0/1); nonzero word == true.
__global__ void k_pass1(const unsigned int* __restrict__ pos,
                        const float* __restrict__ conf) {
    int b = blockIdx.y;
    const unsigned int* P = pos  + (size_t)b * NN;
    const float*        C = conf + (size_t)b * NN;
    float ploss = 0.0f;
    int   pcnt  = 0;
    int stride = gridDim.x * blockDim.x;
    for (int i = blockIdx.x * blockDim.x + threadIdx.x; i < NN; i += stride) {
        unsigned int p = P[i];
        float v = C[i];
        if (p) {
            pcnt++;
            ploss -= log_c(v);
        } else {
            atomicAdd(&g_hist[b][conf_bin(v)], 1);
        }
    }
    // warp reduce (b uniform within a warp: NN is a multiple of 32)
    for (int o = 16; o; o >>= 1) {
        ploss += __shfl_down_sync(0xffffffffu, ploss, o);
        pcnt  += __shfl_down_sync(0xffffffffu, pcnt, o);
    }
    if ((threadIdx.x & 31) == 0) {
        if (ploss != 0.0f) atomicAdd(&g_acc_ph[b], ploss);
        if (pcnt) atomicAdd(&g_numpos[b], pcnt);
    }
}

// ---------------------------------------------------------------------------
__global__ void k_coarse() {
    int t = blockIdx.x * blockDim.x + threadIdx.x;
    if (t >= BB * NBC) return;
    int b = t / NBC, cb = t % NBC;
    int s = 0;
#pragma unroll 8
    for (int f = 0; f < FPC; f++) s += g_hist[b][cb * FPC + f];
    g_coarse[b][cb] = s;
}

// ---------------------------------------------------------------------------
// Collect rand_u candidates below threshold (valid j only).
__global__ void k_cand(const float* __restrict__ u) {
    int b = blockIdx.y;
    int limit = (NN - g_numpos[b]) - 512;   // num_neg - 512
    if (limit > NU) limit = NU;
    if (limit < 0)  limit = 0;
    const float* U = u + (size_t)b * NU;
    int stride = gridDim.x * blockDim.x;
    for (int j = blockIdx.x * blockDim.x + threadIdx.x; j < limit; j += stride) {
        float uu = U[j];
        if (uu < T0) {
            int p = atomicAdd(&g_candcnt[b], 1);
            if (p < CAP_CAND) {
                g_cand_u[b][p] = uu;
                g_cand_j[b][p] = j;
            }
        }
    }
}

// ---------------------------------------------------------------------------
// Exact top-512-smallest-u selection among candidates via O(K^2) rank count.
// Tie-break (u equal -> lower j first) matches jnp.argsort stability.
__global__ void k_select() {
    int b = blockIdx.x;
    int K = min(g_candcnt[b], CAP_CAND);
    __shared__ float su[1024];
    __shared__ int   sj[1024];
    int iters = (K + 1023) / 1024;
    for (int it = 0; it < iters; it++) {
        int i = it * 1024 + threadIdx.x;
        bool active = i < K;
        float ui = active ? g_cand_u[b][i] : 1.0e30f;
        int   ji = active ? g_cand_j[b][i] : 0x7fffffff;
        int rank = 0;
        for (int base = 0; base < K; base += 1024) {
            __syncthreads();
            int k = base + threadIdx.x;
            if (k < K) { su[threadIdx.x] = g_cand_u[b][k]; sj[threadIdx.x] = g_cand_j[b][k]; }
            __syncthreads();
            int lim = min(1024, K - base);
            for (int kk = 0; kk < lim; kk++) {
                float uk = su[kk];
                int   jk = sj[kk];
                rank += (uk < ui) || (uk == ui && jk < ji);
            }
        }
        if (active && rank < 512) {
            int q = atomicAdd(&g_qcnt[b], 1);
            if (q < MAXQ) g_qrank[b][q] = 512 + ji;
        }
    }
}

// ---------------------------------------------------------------------------
// Map each rank query (rank-from-top R among negatives) to (fine bin, rank
// within bin), and assign compact slot ids to interesting bins.
__global__ void k_locate() {
    int b = blockIdx.x;
    int num_neg = NN - g_numpos[b];
    int qn = min(g_qcnt[b], MAXQ);
    for (int q = threadIdx.x; q < qn; q += blockDim.x) {
        int R = g_qrank[b][q];
        if (R >= num_neg) { g_qbin[b][q] = -1; continue; }
        int rem = R;
        int cb = NBC - 1;
        for (; cb >= 0; cb--) {
            int c = g_coarse[b][cb];
            if (rem < c) break;
            rem -= c;
        }
        int bin = -1;
        if (cb >= 0) {
            for (int f = FPC - 1; f >= 0; f--) {
                int fb = cb * FPC + f;
                int h = g_hist[b][fb];
                if (rem < h) { bin = fb; break; }
                rem -= h;
            }
        }
        g_qbin[b][q] = bin;
        g_qt[b][q] = rem;
        if (bin >= 0 && g_slotid[b][bin] == -1) {
            int ns = atomicAdd(&g_nslots[b], 1);   // races may waste a slot; SLOTS has slack
            atomicCAS(&g_slotid[b][bin], -1, ns);
        }
    }
}

// ---------------------------------------------------------------------------
// Gather negatives that fall into interesting bins into compact slots.
__global__ void k_gather(const unsigned int* __restrict__ pos,
                         const float* __restrict__ conf) {
    int b = blockIdx.y;
    const unsigned int* P = pos  + (size_t)b * NN;
    const float*        C = conf + (size_t)b * NN;
    int stride = gridDim.x * blockDim.x;
    for (int i = blockIdx.x * blockDim.x + threadIdx.x; i < NN; i += stride) {
        if (P[i]) continue;
        float v = C[i];
        int s = g_slotid[b][conf_bin(v)];
        if (s >= 0) {
            int p = atomicAdd(&g_slotcnt[b][s], 1);
            if (p < SLOTC) g_slotbuf[b][s][p] = v;
        }
    }
}

// ---------------------------------------------------------------------------
// Exact within-bin value-at-rank (t-th largest, 0-based) + loss accumulation.
__global__ void k_resolve() {
    int b = blockIdx.x;
    int qn = min(g_qcnt[b], MAXQ);
    for (int q = threadIdx.x; q < qn; q += blockDim.x) {
        int bin = g_qbin[b][q];
        if (bin < 0) continue;
        int s = g_slotid[b][bin];
        int n = min(g_slotcnt[b][s], SLOTC);
        int t = g_qt[b][q];
        float v = 0.5f;
        for (int i = 0; i < n; i++) {
            float x = g_slotbuf[b][s][i];
            int gt = 0, eq = 0;
            for (int j2 = 0; j2 < n; j2++) {
                float y = g_slotbuf[b][s][j2];
                gt += (y > x);
                eq += (y == x);
            }
            if (gt <= t && t < gt + eq) { v = x; break; }
        }
        float term = -log_c(1.0f - v);
        if (q < 512) atomicAdd(&g_acc_ph[b], term);
        else         atomicAdd(&g_acc_r[b],  term);
    }
}

// ---------------------------------------------------------------------------
__global__ void k_final(float* __restrict__ out) {
    int b = threadIdx.x;
    if (b < BB) {
        int np = g_numpos[b];
        int nn = NN - np;
        bool has_rem = (nn - 512) > 0;
        float sn = (float)(np + min(512, nn));
        out[b] = has_rem ? (g_acc_ph[b] + g_acc_r[b])
                         : (g_acc_ph[b] / fmaxf(sn, 1.0f));
    }
}

// ===========================================================================
extern "C" void kernel_launch(void* const* d_in, const int* in_sizes, int n_in,
                              void* d_out, int out_size) {
    (void)in_sizes; (void)n_in; (void)out_size;
    const unsigned int* pos  = (const unsigned int*)d_in[0];
    const float*        conf = (const float*)d_in[1];
    const float*        u    = (const float*)d_in[2];
    float*              out  = (float*)d_out;

    k_init<<<4096, 512>>>();                       // 4096*512 == BB*NB exactly
    k_pass1<<<dim3(512, BB), 256>>>(pos, conf);
    k_coarse<<<(BB * NBC + 255) / 256, 256>>>();
    k_cand<<<dim3(256, BB), 256>>>(u);
    k_select<<<BB, 1024>>>();
    k_locate<<<BB, 1024>>>();
    k_gather<<<dim3(512, BB), 256>>>(pos, conf);
    k_resolve<<<BB, 1024>>>();
    k_final<<<1, 32>>>(out);
}

// round 2
// speedup vs baseline: 1.3696x; 1.3696x over previous
#include <cuda_runtime.h>
#include <math.h>
#include <stdint.h>

// ============================================================================
// ClassificationLoss OHEM: B=16, N=1M anchors/image.
//   out[b] = pos_loss + hard_loss(top-512 neg) + rand_loss(512 rank queries)
// Exact value-at-rank via privatized smem histogram (8192 bins) + per-bin
// gather + warp-parallel within-bin selection. No sort.
// ============================================================================

#define BB 16
#define NN (1 << 20)
#define NB 8192                 // fine bins (32KB smem histogram)
#define NBC 128                 // coarse bins
#define FPC (NB / NBC)          // 64
#define NU (NN - 512)
#define NUV (NU / 4)            // 262016 float4s
#define CHUNK (NN / 16)         // 65536 elems per block (16 chunks/image)
#define CAP_CAND 32768
#define T0 0.002f
#define MAXQ 1024
#define SLOTS 1152
#define SLOTC 256

// -------- scratch ----------------------------------------------------------
__device__ int   g_hist[BB][NB];
__device__ int   g_slotid[BB][NB];
__device__ float g_slotbuf[BB][SLOTS][SLOTC];
__device__ int   g_slotcnt[BB][SLOTS];
__device__ int   g_nslots[BB];
__device__ int   g_numpos[BB];
__device__ float g_acc_ph[BB];
__device__ float g_acc_r[BB];
__device__ float g_cand_u[BB][CAP_CAND];
__device__ int   g_cand_j[BB][CAP_CAND];
__device__ int   g_candcnt[BB];
__device__ int   g_qrank[BB][MAXQ];
__device__ int   g_qbin[BB][MAXQ];
__device__ int   g_qt[BB][MAXQ];
__device__ int   g_qcnt[BB];

__device__ __forceinline__ float log_c(float x) {
    return fmaxf(logf(x), -100.0f);
}
__device__ __forceinline__ int conf_bin(float v) {
    int b = (int)(v * (float)NB);
    return b < 0 ? 0 : (b >= NB ? NB - 1 : b);
}

// ---------------------------------------------------------------------------
__global__ void k_init() {
    int tid = blockIdx.x * blockDim.x + threadIdx.x;           // 131072 threads
    // BB*NB == 131072 exactly
    int b = tid >> 13, bin = tid & (NB - 1);
    g_hist[b][bin] = 0;
    g_slotid[b][bin] = -1;
    if (tid < BB * SLOTS) g_slotcnt[tid / SLOTS][tid % SLOTS] = 0;
    if (tid < BB) {
        g_nslots[tid] = 0;
        g_numpos[tid] = 0;
        g_acc_ph[tid] = 0.0f;
        g_acc_r[tid]  = 0.0f;
        g_candcnt[tid] = 0;
    }
}

// ---------------------------------------------------------------------------
// Fused pass: pos count + pos loss + smem-privatized neg histogram + rand_u
// candidate collection (validity filtered later, when num_pos is known).
__global__ void __launch_bounds__(512) k_main(const uint4* __restrict__ pos,
                                              const float4* __restrict__ conf,
                                              const float4* __restrict__ u) {
    __shared__ int sh[NB];                       // 32 KB
    int b = blockIdx.y;
    int chunk = blockIdx.x;                      // 0..15
    int tid = threadIdx.x;

    for (int j = tid; j < NB; j += 512) sh[j] = 0;
    __syncthreads();

    // ---- phase 1: histogram + pos loss over this chunk (65536 elems) ----
    const uint4*  P = pos  + ((size_t)b * NN + (size_t)chunk * CHUNK) / 4;
    const float4* C = conf + ((size_t)b * NN + (size_t)chunk * CHUNK) / 4;
    float ploss = 0.0f;
    int   pcnt  = 0;
#pragma unroll 4
    for (int it = 0; it < CHUNK / 4 / 512; it++) {       // 32 iters
        int i = it * 512 + tid;
        uint4  p = P[i];
        float4 v = C[i];
        if (p.x) { pcnt++; ploss -= log_c(v.x); } else atomicAdd(&sh[conf_bin(v.x)], 1);
        if (p.y) { pcnt++; ploss -= log_c(v.y); } else atomicAdd(&sh[conf_bin(v.y)], 1);
        if (p.z) { pcnt++; ploss -= log_c(v.z); } else atomicAdd(&sh[conf_bin(v.z)], 1);
        if (p.w) { pcnt++; ploss -= log_c(v.w); } else atomicAdd(&sh[conf_bin(v.w)], 1);
    }
    __syncthreads();
    for (int j = tid; j < NB; j += 512) {
        int c = sh[j];
        if (c) atomicAdd(&g_hist[b][j], c);
    }
    for (int o = 16; o; o >>= 1) {
        ploss += __shfl_down_sync(0xffffffffu, ploss, o);
        pcnt  += __shfl_down_sync(0xffffffffu, pcnt, o);
    }
    if ((tid & 31) == 0) {
        if (ploss != 0.0f) atomicAdd(&g_acc_ph[b], ploss);
        if (pcnt) atomicAdd(&g_numpos[b], pcnt);
    }

    // ---- phase 2: rand_u candidates (grid-stride across this image) ----
    const float4* U = u + (size_t)b * NUV;
    for (int vi = chunk * 512 + tid; vi < NUV; vi += 16 * 512) {
        float4 uu = U[vi];
        int j4 = vi * 4;
        if (uu.x < T0) { int p = atomicAdd(&g_candcnt[b], 1); if (p < CAP_CAND) { g_cand_u[b][p] = uu.x; g_cand_j[b][p] = j4;     } }
        if (uu.y < T0) { int p = atomicAdd(&g_candcnt[b], 1); if (p < CAP_CAND) { g_cand_u[b][p] = uu.y; g_cand_j[b][p] = j4 + 1; } }
        if (uu.z < T0) { int p = atomicAdd(&g_candcnt[b], 1); if (p < CAP_CAND) { g_cand_u[b][p] = uu.z; g_cand_j[b][p] = j4 + 2; } }
        if (uu.w < T0) { int p = atomicAdd(&g_candcnt[b], 1); if (p < CAP_CAND) { g_cand_u[b][p] = uu.w; g_cand_j[b][p] = j4 + 3; } }
    }
}

// ---------------------------------------------------------------------------
// Per image: coarse sums + exact top-512-smallest-u selection + rank->bin
// location. One 1024-thread block per image.
__global__ void __launch_bounds__(1024) k_mid() {
    int b = blockIdx.x;
    int tid = threadIdx.x;
    __shared__ int   scoarse[NBC];
    __shared__ float su[1024];
    __shared__ int   sj[1024];

    // coarse sums
    if (tid < NBC) {
        int s = 0;
        int base = tid * FPC;
#pragma unroll 8
        for (int f = 0; f < FPC; f++) s += g_hist[b][base + f];
        scoarse[tid] = s;
    }
    // query init
    if (tid == 0) g_qcnt[b] = 512;
    if (tid < 512) g_qrank[b][tid] = tid;      // hard ranks 0..511
    __syncthreads();

    // ---- select: exact rank of each candidate among valid candidates ----
    int num_neg = NN - g_numpos[b];
    int limit = num_neg - 512;                 // valid: j < limit
    int K = min(g_candcnt[b], CAP_CAND);
    int iters = (K + 1023) / 1024;
    for (int it = 0; it < iters; it++) {
        int i = it * 1024 + tid;
        bool active = (i < K);
        float ui = 1.0e30f; int ji = 0x7fffffff;
        if (active) {
            ji = g_cand_j[b][i];
            ui = (ji < limit) ? g_cand_u[b][i] : 1.0e30f;
        }
        bool valid = active && (ji < limit);
        int rank = 0;
        for (int base = 0; base < K; base += 1024) {
            __syncthreads();
            int k = base + tid;
            if (k < K) {
                int jk = g_cand_j[b][k];
                sj[tid] = jk;
                su[tid] = (jk < limit) ? g_cand_u[b][k] : 1.0e30f;
            }
            __syncthreads();
            int lim = min(1024, K - base);
            for (int kk = 0; kk < lim; kk++) {
                float uk = su[kk];
                int   jk = sj[kk];
                rank += (uk < ui) || (uk == ui && jk < ji);
            }
        }
        if (valid && rank < 512) {
            int q = atomicAdd(&g_qcnt[b], 1);
            if (q < MAXQ) g_qrank[b][q] = 512 + ji;
        }
    }
    __syncthreads();

    // ---- locate: rank (from top, among negs) -> (fine bin, within-bin t) --
    int qn = min(g_qcnt[b], MAXQ);
    for (int q = tid; q < qn; q += 1024) {
        int R = g_qrank[b][q];
        if (R >= num_neg) { g_qbin[b][q] = -1; continue; }
        int rem = R;
        int cb = NBC - 1;
        for (; cb >= 0; cb--) {
            int c = scoarse[cb];
            if (rem < c) break;
            rem -= c;
        }
        int bin = -1;
        if (cb >= 0) {
            for (int f = FPC - 1; f >= 0; f--) {
                int fb = cb * FPC + f;
                int h = g_hist[b][fb];
                if (rem < h) { bin = fb; break; }
                rem -= h;
            }
        }
        g_qbin[b][q] = bin;
        g_qt[b][q] = rem;
        if (bin >= 0 && g_slotid[b][bin] == -1) {
            int ns = atomicAdd(&g_nslots[b], 1);
            atomicCAS(&g_slotid[b][bin], -1, ns);
        }
    }
}

// ---------------------------------------------------------------------------
// Gather negatives in interesting bins; slot table staged in smem.
__global__ void __launch_bounds__(512) k_gather(const uint4* __restrict__ pos,
                                                const float4* __restrict__ conf) {
    __shared__ int sid[NB];                    // 32 KB
    int b = blockIdx.y;
    int chunk = blockIdx.x;
    int tid = threadIdx.x;
    for (int j = tid; j < NB; j += 512) sid[j] = g_slotid[b][j];
    __syncthreads();

    const uint4*  P = pos  + ((size_t)b * NN + (size_t)chunk * CHUNK) / 4;
    const float4* C = conf + ((size_t)b * NN + (size_t)chunk * CHUNK) / 4;
#pragma unroll 4
    for (int it = 0; it < CHUNK / 4 / 512; it++) {
        int i = it * 512 + tid;
        uint4  p = P[i];
        float4 v = C[i];
        int s;
        if (!p.x && (s = sid[conf_bin(v.x)]) >= 0) { int w = atomicAdd(&g_slotcnt[b][s], 1); if (w < SLOTC) g_slotbuf[b][s][w] = v.x; }
        if (!p.y && (s = sid[conf_bin(v.y)]) >= 0) { int w = atomicAdd(&g_slotcnt[b][s], 1); if (w < SLOTC) g_slotbuf[b][s][w] = v.y; }
        if (!p.z && (s = sid[conf_bin(v.z)]) >= 0) { int w = atomicAdd(&g_slotcnt[b][s], 1); if (w < SLOTC) g_slotbuf[b][s][w] = v.z; }
        if (!p.w && (s = sid[conf_bin(v.w)]) >= 0) { int w = atomicAdd(&g_slotcnt[b][s], 1); if (w < SLOTC) g_slotbuf[b][s][w] = v.w; }
    }
}

// ---------------------------------------------------------------------------
// One warp per query: exact t-th-largest within the gathered bin.
__global__ void __launch_bounds__(1024) k_resolve() {
    __shared__ float vals[32][SLOTC];          // 32 KB
    int b = blockIdx.y;
    int w = threadIdx.x >> 5, lane = threadIdx.x & 31;
    int q = blockIdx.x * 32 + w;
    int qn = min(g_qcnt[b], MAXQ);
    if (q >= qn) return;
    int bin = g_qbin[b][q];
    if (bin < 0) return;
    int s = g_slotid[b][bin];
    if (s < 0) return;
    int n = min(g_slotcnt[b][s], SLOTC);
    int t = g_qt[b][q];

    for (int i = lane; i < n; i += 32) vals[w][i] = g_slotbuf[b][s][i];
    __syncwarp();

    bool fire = false; float xv = 0.0f;
    for (int i = lane; i < n; i += 32) {
        float x = vals[w][i];
        int gt = 0, eqb = 0;
        for (int k = 0; k < n; k++) {
            float y = vals[w][k];
            gt  += (y > x);
            eqb += (y == x) && (k < i);
        }
        if (gt + eqb == t) { fire = true; xv = x; }
    }
    if (fire) {
        float term = -log_c(1.0f - xv);
        if (q < 512) atomicAdd(&g_acc_ph[b], term);
        else         atomicAdd(&g_acc_r[b],  term);
    }
}

// ---------------------------------------------------------------------------
__global__ void k_final(float* __restrict__ out) {
    int b = threadIdx.x;
    if (b < BB) {
        int np = g_numpos[b];
        int nn = NN - np;
        bool has_rem = (nn - 512) > 0;
        float sn = (float)(np + min(512, nn));
        out[b] = has_rem ? (g_acc_ph[b] + g_acc_r[b])
                         : (g_acc_ph[b] / fmaxf(sn, 1.0f));
    }
}

// ===========================================================================
extern "C" void kernel_launch(void* const* d_in, const int* in_sizes, int n_in,
                              void* d_out, int out_size) {
    (void)in_sizes; (void)n_in; (void)out_size;
    const uint4*  pos  = (const uint4*)d_in[0];
    const float4* conf = (const float4*)d_in[1];
    const float4* u    = (const float4*)d_in[2];
    float*        out  = (float*)d_out;

    k_init<<<256, 512>>>();                        // 131072 threads == BB*NB
    k_main<<<dim3(16, BB), 512>>>(pos, conf, u);
    k_mid<<<BB, 1024>>>();
    k_gather<<<dim3(16, BB), 512>>>(pos, conf);
    k_resolve<<<dim3(32, BB), 1024>>>();
    k_final<<<1, 32>>>(out);
}

// round 5
// speedup vs baseline: 1.6870x; 1.2317x over previous
#include <cuda_runtime.h>
#include <math.h>
#include <stdint.h>

// ============================================================================
// ClassificationLoss OHEM: B=16, N=1M anchors/image. Exact value-at-rank via
// privatized smem histogram (8192 bins, 16-bit-packed, 16KB) + slot gather
// (16-bit slot table, 16KB) + O(n) sub-histogram selection.
// ============================================================================

#define BB 16
#define NN (1 << 20)
#define NB 8192                 // fine bins
#define NBH (NB / 2)            // packed 32-bit words (16KB smem)
#define NBC 128                 // coarse bins
#define FPC (NB / NBC)          // 64
#define NU (NN - 512)
#define NUV (NU / 4)            // 262016 float4s
#define NCHUNK 64
#define CHUNK (NN / NCHUNK)     // 16384 elems per block
#define VITERS (CHUNK / 4 / 512)// 8
#define CAP_CAND 8192
#define T0 0.002f
#define MAXQ 1024
#define SLOTS 1152
#define SLOTC 256

// -------- scratch (static device globals; same footprint as R2-pass) -------
__device__ int            g_hist[BB][NB];
__device__ int            g_slotid[BB][NB];
__device__ float          g_slotbuf[BB][SLOTS][SLOTC];   // 18.9 MB
__device__ int            g_slotcnt[BB][SLOTS];
__device__ int            g_nslots[BB];
__device__ int            g_numpos[BB];
__device__ float          g_acc_ph[BB];
__device__ float          g_acc_r[BB];
__device__ float          g_cand_u[BB][CAP_CAND];
__device__ int            g_cand_j[BB][CAP_CAND];
__device__ int            g_candcnt[BB];
__device__ int            g_qrank[BB][MAXQ];
__device__ int            g_qbin[BB][MAXQ];
__device__ int            g_qt[BB][MAXQ];
__device__ int            g_qcnt[BB];
__device__ unsigned short g_slotid16[BB][NB];            // staged 16-bit table

__device__ __forceinline__ float log_c(float x) {
    return fmaxf(logf(x), -100.0f);
}
__device__ __forceinline__ int conf_bin(float v) {
    int b = (int)(v * (float)NB);
    return b < 0 ? 0 : (b >= NB ? NB - 1 : b);
}
// sub-bin within a fine bin (256 sub-bins), consistent with conf_bin
__device__ __forceinline__ int sub_idx(float v, int bin) {
    float frac = v * (float)NB - (float)bin;
    int s = (int)(frac * 256.0f);
    return s < 0 ? 0 : (s > 255 ? 255 : s);
}

// ---------------------------------------------------------------------------
__global__ void k_init() {
    int tid = blockIdx.x * blockDim.x + threadIdx.x;   // 131072 == BB*NB
    if (tid < BB * NB) {
        int b = tid >> 13, bin = tid & (NB - 1);
        g_hist[b][bin] = 0;
        g_slotid[b][bin] = -1;
        g_slotid16[b][bin] = 0xFFFFu;
    }
    if (tid < BB * SLOTS) g_slotcnt[tid / SLOTS][tid % SLOTS] = 0;
    if (tid < BB) {
        g_nslots[tid] = 0;
        g_numpos[tid] = 0;
        g_acc_ph[tid] = 0.0f;
        g_acc_r[tid]  = 0.0f;
        g_candcnt[tid] = 0;
    }
}

// ---------------------------------------------------------------------------
// Fused pass 1: pos count + pos loss + smem-privatized (16-bit packed)
// histogram + rand_u candidate collection.
__global__ void __launch_bounds__(512) k_main(const uint4* __restrict__ pos,
                                              const float4* __restrict__ conf,
                                              const float4* __restrict__ u) {
    __shared__ unsigned int sh[NBH];             // 16 KB: two 16-bit bins/word
    int b = blockIdx.y;
    int chunk = blockIdx.x;                      // 0..63
    int tid = threadIdx.x;

    for (int j = tid; j < NBH; j += 512) sh[j] = 0u;
    __syncthreads();

    const uint4*  P = pos  + ((size_t)b * NN + (size_t)chunk * CHUNK) / 4;
    const float4* C = conf + ((size_t)b * NN + (size_t)chunk * CHUNK) / 4;
    float ploss = 0.0f;
    int   pcnt  = 0;
#pragma unroll 2
    for (int it = 0; it < VITERS; it++) {
        int i = it * 512 + tid;
        uint4  p = P[i];
        float4 v = C[i];
        int bin;
        if (p.x) { pcnt++; ploss -= log_c(v.x); } else { bin = conf_bin(v.x); atomicAdd(&sh[bin >> 1], 1u << ((bin & 1) * 16)); }
        if (p.y) { pcnt++; ploss -= log_c(v.y); } else { bin = conf_bin(v.y); atomicAdd(&sh[bin >> 1], 1u << ((bin & 1) * 16)); }
        if (p.z) { pcnt++; ploss -= log_c(v.z); } else { bin = conf_bin(v.z); atomicAdd(&sh[bin >> 1], 1u << ((bin & 1) * 16)); }
        if (p.w) { pcnt++; ploss -= log_c(v.w); } else { bin = conf_bin(v.w); atomicAdd(&sh[bin >> 1], 1u << ((bin & 1) * 16)); }
    }

    // rand_u candidate collection (validity filtered later, once num_pos known)
    const float4* U = u + (size_t)b * NUV;
    for (int vi = chunk * 512 + tid; vi < NUV; vi += NCHUNK * 512) {
        float4 uu = U[vi];
        int j4 = vi * 4;
        if (uu.x < T0) { int p = atomicAdd(&g_candcnt[b], 1); if (p < CAP_CAND) { g_cand_u[b][p] = uu.x; g_cand_j[b][p] = j4;     } }
        if (uu.y < T0) { int p = atomicAdd(&g_candcnt[b], 1); if (p < CAP_CAND) { g_cand_u[b][p] = uu.y; g_cand_j[b][p] = j4 + 1; } }
        if (uu.z < T0) { int p = atomicAdd(&g_candcnt[b], 1); if (p < CAP_CAND) { g_cand_u[b][p] = uu.z; g_cand_j[b][p] = j4 + 2; } }
        if (uu.w < T0) { int p = atomicAdd(&g_candcnt[b], 1); if (p < CAP_CAND) { g_cand_u[b][p] = uu.w; g_cand_j[b][p] = j4 + 3; } }
    }

    for (int o = 16; o; o >>= 1) {
        ploss += __shfl_down_sync(0xffffffffu, ploss, o);
        pcnt  += __shfl_down_sync(0xffffffffu, pcnt, o);
    }
    if ((tid & 31) == 0) {
        if (ploss != 0.0f) atomicAdd(&g_acc_ph[b], ploss);
        if (pcnt) atomicAdd(&g_numpos[b], pcnt);
    }

    __syncthreads();
    for (int j = tid; j < NBH; j += 512) {
        unsigned int w = sh[j];
        unsigned int lo = w & 0xFFFFu, hi = w >> 16;
        if (lo) atomicAdd(&g_hist[b][2 * j],     (int)lo);
        if (hi) atomicAdd(&g_hist[b][2 * j + 1], (int)hi);
    }
}

// ---------------------------------------------------------------------------
// Per image: coarse sums + exact top-512-smallest-u + rank->bin location +
// 16-bit slot table build.
__global__ void __launch_bounds__(1024) k_mid() {
    int b = blockIdx.x;
    int tid = threadIdx.x;
    __shared__ int   scoarse[NBC];
    __shared__ float su[1024];
    __shared__ int   sj[1024];

    if (tid < NBC) {
        int s = 0;
        int base = tid * FPC;
#pragma unroll 8
        for (int f = 0; f < FPC; f++) s += g_hist[b][base + f];
        scoarse[tid] = s;
    }
    if (tid == 0) g_qcnt[b] = 512;
    if (tid < 512) g_qrank[b][tid] = tid;      // hard ranks 0..511
    __syncthreads();

    int num_neg = NN - g_numpos[b];
    int limit = num_neg - 512;                 // valid candidates: j < limit
    int K = min(g_candcnt[b], CAP_CAND);
    int iters = (K + 1023) / 1024;
    for (int it = 0; it < iters; it++) {
        int i = it * 1024 + tid;
        bool active = (i < K);
        float ui = 1.0e30f; int ji = 0x7fffffff;
        if (active) {
            ji = g_cand_j[b][i];
            ui = (ji < limit) ? g_cand_u[b][i] : 1.0e30f;
        }
        bool valid = active && (ji < limit);
        int rank = 0;
        for (int base = 0; base < K; base += 1024) {
            __syncthreads();
            int k = base + tid;
            if (k < K) {
                int jk = g_cand_j[b][k];
                sj[tid] = jk;
                su[tid] = (jk < limit) ? g_cand_u[b][k] : 1.0e30f;
            }
            __syncthreads();
            int lim = min(1024, K - base);
            for (int kk = 0; kk < lim; kk++) {
                float uk = su[kk];
                int   jk = sj[kk];
                rank += (uk < ui) || (uk == ui && jk < ji);
            }
        }
        if (valid && rank < 512) {
            int q = atomicAdd(&g_qcnt[b], 1);
            if (q < MAXQ) g_qrank[b][q] = 512 + ji;
        }
    }
    __syncthreads();

    int qn = min(g_qcnt[b], MAXQ);
    for (int q = tid; q < qn; q += 1024) {
        int R = g_qrank[b][q];
        if (R >= num_neg) { g_qbin[b][q] = -1; continue; }
        int rem = R;
        int cb = NBC - 1;
        for (; cb >= 0; cb--) {
            int c = scoarse[cb];
            if (rem < c) break;
            rem -= c;
        }
        int bin = -1;
        if (cb >= 0) {
            for (int f = FPC - 1; f >= 0; f--) {
                int fb = cb * FPC + f;
                int h = g_hist[b][fb];
                if (rem < h) { bin = fb; break; }
                rem -= h;
            }
        }
        g_qbin[b][q] = bin;
        g_qt[b][q] = rem;
        if (bin >= 0 && g_slotid[b][bin] == -1) {
            int ns = atomicAdd(&g_nslots[b], 1);   // waste-on-race ok; SLOTS slack
            if (atomicCAS(&g_slotid[b][bin], -1, ns) == -1)
                g_slotid16[b][bin] = (unsigned short)ns;
        }
    }
}

// ---------------------------------------------------------------------------
// Pass 2: gather negatives in interesting bins; 16-bit slot table in smem.
__global__ void __launch_bounds__(512) k_gather(const uint4* __restrict__ pos,
                                                const float4* __restrict__ conf) {
    __shared__ unsigned short sid[NB];         // 16 KB
    int b = blockIdx.y;
    int chunk = blockIdx.x;
    int tid = threadIdx.x;
    // vectorized staging (NB/2 uint loads)
    const unsigned int* src = (const unsigned int*)g_slotid16[b];
    unsigned int* dst = (unsigned int*)sid;
    for (int j = tid; j < NB / 2; j += 512) dst[j] = src[j];
    __syncthreads();

    const uint4*  P = pos  + ((size_t)b * NN + (size_t)chunk * CHUNK) / 4;
    const float4* C = conf + ((size_t)b * NN + (size_t)chunk * CHUNK) / 4;
#pragma unroll 2
    for (int it = 0; it < VITERS; it++) {
        int i = it * 512 + tid;
        uint4  p = P[i];
        float4 v = C[i];
        unsigned short s;
        if (!p.x && (s = sid[conf_bin(v.x)]) != 0xFFFFu) { int w = atomicAdd(&g_slotcnt[b][s], 1); if (w < SLOTC) g_slotbuf[b][s][w] = v.x; }
        if (!p.y && (s = sid[conf_bin(v.y)]) != 0xFFFFu) { int w = atomicAdd(&g_slotcnt[b][s], 1); if (w < SLOTC) g_slotbuf[b][s][w] = v.y; }
        if (!p.z && (s = sid[conf_bin(v.z)]) != 0xFFFFu) { int w = atomicAdd(&g_slotcnt[b][s], 1); if (w < SLOTC) g_slotbuf[b][s][w] = v.z; }
        if (!p.w && (s = sid[conf_bin(v.w)]) != 0xFFFFu) { int w = atomicAdd(&g_slotcnt[b][s], 1); if (w < SLOTC) g_slotbuf[b][s][w] = v.w; }
    }
}

// ---------------------------------------------------------------------------
// One warp per query: t-th largest within gathered bin, O(n) via 256-sub-bin
// histogram + suffix scan + tiny exact finish.
__global__ void __launch_bounds__(256) k_resolve() {
    __shared__ float vals[8][SLOTC];           // 8 KB
    __shared__ int   subh[8][256];             // 8 KB
    __shared__ float mval[8][32];
    __shared__ int   mcnt[8];

    int b = blockIdx.y;
    int w = threadIdx.x >> 5, lane = threadIdx.x & 31;
    int q = blockIdx.x * 8 + w;                // 128 * 8 = 1024 = MAXQ
    int qn = min(g_qcnt[b], MAXQ);
    if (q >= qn) return;
    int bin = g_qbin[b][q];
    if (bin < 0) return;
    int s = g_slotid[b][bin];
    if (s < 0) return;
    int n = min(g_slotcnt[b][s], SLOTC);
    int t = g_qt[b][q];

    for (int i = lane; i < n; i += 32) vals[w][i] = g_slotbuf[b][s][i];
    for (int k = lane; k < 256; k += 32) subh[w][k] = 0;
    if (lane == 0) mcnt[w] = 0;
    __syncwarp();
    for (int i = lane; i < n; i += 32) atomicAdd(&subh[w][sub_idx(vals[w][i], bin)], 1);
    __syncwarp();

    // lane L owns sub-bins [L*8, L*8+8); larger sub == larger value
    int h[8], lt = 0;
#pragma unroll
    for (int k = 0; k < 8; k++) { h[k] = subh[w][lane * 8 + k]; lt += h[k]; }
    int s1 = lt;
#pragma unroll
    for (int o = 1; o < 32; o <<= 1) {
        int t2 = __shfl_down_sync(0xffffffffu, s1, o);
        if (lane + o < 32) s1 += t2;
    }
    int cum = s1 - lt;                          // items strictly above this lane's range
    int found = -1, tp_local = 0;
#pragma unroll
    for (int k = 7; k >= 0; k--) {
        int hh = h[k];
        if (found < 0 && t >= cum && t < cum + hh) { found = lane * 8 + k; tp_local = t - cum; }
        cum += hh;
    }
    unsigned bal = __ballot_sync(0xffffffffu, found >= 0);
    if (!bal) return;
    int src = __ffs(bal) - 1;
    int sel_sub = __shfl_sync(0xffffffffu, found, src);
    int tp = __shfl_sync(0xffffffffu, tp_local, src);

    for (int i = lane; i < n; i += 32) {
        float x = vals[w][i];
        if (sub_idx(x, bin) == sel_sub) {
            int p = atomicAdd(&mcnt[w], 1);
            if (p < 32) mval[w][p] = x;
        }
    }
    __syncwarp();
    if (lane == 0) {
        int m = min(mcnt[w], 32);
        float res = 0.5f;
        for (int a = 0; a < m; a++) {
            float x = mval[w][a];
            int gt = 0, eq = 0;
            for (int c = 0; c < m; c++) {
                float y = mval[w][c];
                gt += (y > x);
                eq += (y == x);
            }
            if (gt <= tp && tp < gt + eq) { res = x; break; }
        }
        float term = -log_c(1.0f - res);
        if (q < 512) atomicAdd(&g_acc_ph[b], term);
        else         atomicAdd(&g_acc_r[b],  term);
    }
}

// ---------------------------------------------------------------------------
__global__ void k_final(float* __restrict__ out) {
    int b = threadIdx.x;
    if (b < BB) {
        int np = g_numpos[b];
        int nn = NN - np;
        bool has_rem = (nn - 512) > 0;
        float sn = (float)(np + min(512, nn));
        out[b] = has_rem ? (g_acc_ph[b] + g_acc_r[b])
                         : (g_acc_ph[b] / fmaxf(sn, 1.0f));
    }
}

// ===========================================================================
extern "C" void kernel_launch(void* const* d_in, const int* in_sizes, int n_in,
                              void* d_out, int out_size) {
    (void)in_sizes; (void)n_in; (void)out_size;
    const uint4*  pos  = (const uint4*)d_in[0];
    const float4* conf = (const float4*)d_in[1];
    const float4* u    = (const float4*)d_in[2];
    float*        out  = (float*)d_out;

    k_init<<<256, 512>>>();                        // 131072 threads == BB*NB
    k_main<<<dim3(NCHUNK, BB), 512>>>(pos, conf, u);
    k_mid<<<BB, 1024>>>();
    k_gather<<<dim3(NCHUNK, BB), 512>>>(pos, conf);
    k_resolve<<<dim3(128, BB), 256>>>();
    k_final<<<1, 32>>>(out);
}